// round 7
// baseline (speedup 1.0000x reference)
#include <cuda_runtime.h>
#include <cuda_fp16.h>

// OLCNN fused grouped-MLP, round 6.
// R5 post-mortem: smem weights added addressing ALU + L1tex wavefronts and lost
// occupancy. This round: weights via 128-bit *global* loads (LDG floor 4/SMSP,
// broadcast = 1 wavefront, uniform UR+imm addressing, L1-resident), rows padded
// to 10 ulls [w0..w8, bias] so each 9-dot is exactly 5x LDG.128.
// Body reverts to the proven R3 shape (2 elem/thread f32x2, fp16 smem inputs,
// 128 thr, 5 blocks/SM), with conflict-free KPAD=82 input stride.

typedef unsigned long long ull;

#define NT    128     // threads per block
#define EPB   256     // elements per block (2 per thread)
#define KDIM  81
#define KPAD  82      // element stride in halfs (164 B; 41*i mod 32 bijective)

// weight blob: rows of 10 ulls [w0..w8, bias]; Wo rows of 6 [w0..w3, bias, pad]
#define OFF_C 0       // 81 rows x 10
#define OFF_H 810     // 27 rows x 10
#define OFF_M 1080    // 12 rows x 10
#define OFF_O 1200    // 4 rows x 6
#define NPREP 1224

__device__ ull gPrep[NPREP];

__device__ __forceinline__ ull dupf(float v) {
    unsigned int b = __float_as_uint(v);
    return ((ull)b << 32) | (ull)b;
}

// Fold sigmoid(a)=0.5*tanh(a/2)+0.5 through the network (validated R2-R5).
__global__ void prep_kernel(const float* __restrict__ Wc, const float* __restrict__ bc,
                            const float* __restrict__ Wh, const float* __restrict__ bh,
                            const float* __restrict__ Wm, const float* __restrict__ bm,
                            const float* __restrict__ Wo, const float* __restrict__ bo) {
    int t = threadIdx.x;
    // conv rows
    for (int r = t; r < 81; r += blockDim.x) {
        #pragma unroll
        for (int p = 0; p < 9; p++)
            gPrep[OFF_C + r * 10 + p] = dupf(0.5f * Wc[r * 9 + p]);
        gPrep[OFF_C + r * 10 + 9] = dupf(0.5f * bc[r]);
    }
    // hidden rows
    for (int r = t; r < 27; r += blockDim.x) {
        float s = 0.f;
        #pragma unroll
        for (int p = 0; p < 9; p++) {
            s += Wh[r * 9 + p];
            gPrep[OFF_H + r * 10 + p] = dupf(0.25f * Wh[r * 9 + p]);
        }
        gPrep[OFF_H + r * 10 + 9] = dupf(0.5f * bh[r] + 0.25f * s);
    }
    // middle rows
    for (int r = t; r < 12; r += blockDim.x) {
        float s = 0.f;
        #pragma unroll
        for (int p = 0; p < 9; p++) {
            s += Wm[r * 9 + p];
            gPrep[OFF_M + r * 10 + p] = dupf(0.25f * Wm[r * 9 + p]);
        }
        gPrep[OFF_M + r * 10 + 9] = dupf(0.5f * bm[r] + 0.25f * s);
    }
    // output rows
    for (int r = t; r < 4; r += blockDim.x) {
        float s = 0.f;
        #pragma unroll
        for (int p = 0; p < 4; p++) {
            s += Wo[r * 4 + p];
            gPrep[OFF_O + r * 6 + p] = dupf(0.5f * Wo[r * 4 + p]);
        }
        gPrep[OFF_O + r * 6 + 4] = dupf(bo[r] + 0.5f * s);
        gPrep[OFF_O + r * 6 + 5] = 0ull;
    }
}

__device__ __forceinline__ ull ffma2(ull a, ull b, ull c) {
    ull d;
    asm("fma.rn.f32x2 %0, %1, %2, %3;" : "=l"(d) : "l"(a), "l"(b), "l"(c));
    return d;
}
__device__ __forceinline__ ull pack2(float lo, float hi) {
    ull r;
    asm("mov.b64 %0, {%1, %2};" : "=l"(r) : "f"(lo), "f"(hi));
    return r;
}
__device__ __forceinline__ void unpack2(ull v, float& lo, float& hi) {
    asm("mov.b64 {%0, %1}, %2;" : "=f"(lo), "=f"(hi) : "l"(v));
}
__device__ __forceinline__ ull tanh2(ull v) {
    float lo, hi;
    unpack2(v, lo, hi);
    asm("tanh.approx.f32 %0, %0;" : "+f"(lo));
    asm("tanh.approx.f32 %0, %0;" : "+f"(hi));
    return pack2(lo, hi);
}

// 9-dot + bias from a 10-ull row: 5x LDG.128 (broadcast, UR+imm addressing)
__device__ __forceinline__ ull dot9(const ull* __restrict__ row, const ull* __restrict__ v) {
    const ulonglong2* __restrict__ r2 = reinterpret_cast<const ulonglong2*>(row);
    ulonglong2 w01 = __ldg(r2 + 0);
    ulonglong2 w23 = __ldg(r2 + 1);
    ulonglong2 w45 = __ldg(r2 + 2);
    ulonglong2 w67 = __ldg(r2 + 3);
    ulonglong2 w8b = __ldg(r2 + 4);       // {w8, bias}
    ull acc = w8b.y;
    acc = ffma2(v[0], w01.x, acc);
    acc = ffma2(v[1], w01.y, acc);
    acc = ffma2(v[2], w23.x, acc);
    acc = ffma2(v[3], w23.y, acc);
    acc = ffma2(v[4], w45.x, acc);
    acc = ffma2(v[5], w45.y, acc);
    acc = ffma2(v[6], w67.x, acc);
    acc = ffma2(v[7], w67.y, acc);
    acc = ffma2(v[8], w8b.x, acc);
    return acc;
}

__global__ __launch_bounds__(NT, 5)
void olcnn_kernel(const float* __restrict__ x, float* __restrict__ out) {
    __shared__ __half xs[EPB * KPAD];     // 41984 B

    const int tid = threadIdx.x;
    const long long blk = blockIdx.x;

    // ---- stage inputs: coalesced float4 -> fp16, element stride KPAD ----
    {
        const float4* __restrict__ src =
            reinterpret_cast<const float4*>(x + blk * (long long)(EPB * KDIM));
        for (int i = tid; i < (EPB * KDIM) / 4; i += NT) {
            float4 v = src[i];
            int f = i * 4;
            int e = f / KDIM;
            int k = f - e * KDIM;
            if (k <= KDIM - 4) {
                __half* d = xs + e * KPAD + k;
                d[0] = __float2half_rn(v.x);
                d[1] = __float2half_rn(v.y);
                d[2] = __float2half_rn(v.z);
                d[3] = __float2half_rn(v.w);
            } else {
                float vv[4] = {v.x, v.y, v.z, v.w};
                #pragma unroll
                for (int j = 0; j < 4; j++) {
                    int kk = k + j, ee = e;
                    if (kk >= KDIM) { kk -= KDIM; ee++; }
                    xs[ee * KPAD + kk] = __float2half_rn(vv[j]);
                }
            }
        }
    }
    __syncthreads();

    // thread handles elements e0=tid, e1=tid+128
    const __half* __restrict__ xa = xs + tid * KPAD;
    const __half* __restrict__ xb = xs + (tid + NT) * KPAD;

    const ull* __restrict__ W = gPrep;

    ull lg[4];
    {
        const ulonglong2* __restrict__ o2 = reinterpret_cast<const ulonglong2*>(W + OFF_O);
        #pragma unroll
        for (int c = 0; c < 4; c++) lg[c] = __ldg(o2 + c * 3 + 2).x;   // bias at row[4]
    }

    #pragma unroll
    for (int G = 0; G < 3; G++) {
        ull h[9];

        #pragma unroll
        for (int s = 0; s < 3; s++) {
            const int g  = 3 * G + s;
            const int gr = g / 3, gc = g % 3;

            ull px[9];
            #pragma unroll
            for (int p = 0; p < 9; p++) {
                const int k = (3 * gr + p / 3) * 9 + (3 * gc + p % 3);
                px[p] = pack2(__half2float(xa[k]), __half2float(xb[k]));
            }

            // conv: 9 kernels -> tanh
            ull f[9];
            #pragma unroll
            for (int k = 0; k < 9; k++)
                f[k] = tanh2(dot9(W + OFF_C + (g * 9 + k) * 10, px));

            // hidden: 3 neurons -> tanh
            #pragma unroll
            for (int n = 0; n < 3; n++)
                h[s * 3 + n] = tanh2(dot9(W + OFF_H + (g * 3 + n) * 10, f));
        }

        // middle group G: 4 neurons -> tanh -> fold into logits
        #pragma unroll
        for (int n = 0; n < 4; n++) {
            ull mv = tanh2(dot9(W + OFF_M + (G * 4 + n) * 10, h));

            const ulonglong2* __restrict__ oG =
                reinterpret_cast<const ulonglong2*>(W + OFF_O + G * 6);
            ulonglong2 w01 = __ldg(oG + 0);
            ulonglong2 w23 = __ldg(oG + 1);
            ull wo = (n == 0) ? w01.x : (n == 1) ? w01.y : (n == 2) ? w23.x : w23.y;
            lg[G] = ffma2(mv, wo, lg[G]);
            if (G == 0) {
                const ulonglong2* __restrict__ o3 =
                    reinterpret_cast<const ulonglong2*>(W + OFF_O + 3 * 6);
                ulonglong2 u01 = __ldg(o3 + 0);
                ulonglong2 u23 = __ldg(o3 + 1);
                ull wo3 = (n == 0) ? u01.x : (n == 1) ? u01.y : (n == 2) ? u23.x : u23.y;
                lg[3] = ffma2(mv, wo3, lg[3]);
            }
        }
    }

    float lo[4], hi[4];
    #pragma unroll
    for (int c = 0; c < 4; c++) unpack2(lg[c], lo[c], hi[c]);

    float4* __restrict__ o4 = reinterpret_cast<float4*>(out) + blk * EPB;
    o4[tid]      = make_float4(lo[0], lo[1], lo[2], lo[3]);
    o4[tid + NT] = make_float4(hi[0], hi[1], hi[2], hi[3]);
}

extern "C" void kernel_launch(void* const* d_in, const int* in_sizes, int n_in,
                              void* d_out, int out_size) {
    const float* x = (const float*)d_in[0];

    prep_kernel<<<1, 128>>>((const float*)d_in[1], (const float*)d_in[2],
                            (const float*)d_in[3], (const float*)d_in[4],
                            (const float*)d_in[5], (const float*)d_in[6],
                            (const float*)d_in[7], (const float*)d_in[8]);

    const int B = in_sizes[0] / KDIM;        // 524288
    const int nblocks = B / EPB;             // 2048

    olcnn_kernel<<<nblocks, NT>>>(x, (float*)d_out);
}

// round 10
// speedup vs baseline: 2.2044x; 2.2044x over previous
#include <cuda_runtime.h>
#include <cuda_fp16.h>

// OLCNN fused grouped-MLP, round 7.
// R6 post-mortem: weight-port ranking measured LDC < LDS < LDG; R3 (LDC.64)
// was never constant-port bound — it was occupancy-starved: static 41.5KB smem
// with default L1 carveout => only 2 resident blocks (occ 28.8% ~= 8 warps/SM).
// This round = exact R3 body + dynamic smem + carveout/maxdynsmem attributes
// to get 5 blocks/SM = 20 warps.

typedef unsigned long long ull;

#define NTHREADS 128
#define ELEMS    256     // per block (2 per thread)
#define KDIM     81

// packed-weight blob offsets (ull units)
#define OFF_WC 0
#define OFF_BC 729
#define OFF_WH 810
#define OFF_BH 1053
#define OFF_WM 1080
#define OFF_BM 1188
#define OFF_WO 1200
#define OFF_BO 1216
#define NPREP  1220

__device__   ull gPrep[NPREP];
__constant__ ull cPrep[NPREP];

__device__ __forceinline__ ull dupf(float v) {
    unsigned int b = __float_as_uint(v);
    return ((ull)b << 32) | (ull)b;
}

// Fold sigmoid(a)=0.5*tanh(a/2)+0.5 through the network (validated R2-R6).
__global__ void prep_kernel(const float* __restrict__ Wc, const float* __restrict__ bc,
                            const float* __restrict__ Wh, const float* __restrict__ bh,
                            const float* __restrict__ Wm, const float* __restrict__ bm,
                            const float* __restrict__ Wo, const float* __restrict__ bo) {
    int t = threadIdx.x;
    for (int i = t; i < 729; i += blockDim.x) gPrep[OFF_WC + i] = dupf(0.5f  * Wc[i]);
    for (int i = t; i < 81;  i += blockDim.x) gPrep[OFF_BC + i] = dupf(0.5f  * bc[i]);
    for (int i = t; i < 243; i += blockDim.x) gPrep[OFF_WH + i] = dupf(0.25f * Wh[i]);
    for (int i = t; i < 27;  i += blockDim.x) {
        float s = 0.f;
        #pragma unroll
        for (int p = 0; p < 9; p++) s += Wh[i * 9 + p];
        gPrep[OFF_BH + i] = dupf(0.5f * bh[i] + 0.25f * s);
    }
    for (int i = t; i < 108; i += blockDim.x) gPrep[OFF_WM + i] = dupf(0.25f * Wm[i]);
    for (int i = t; i < 12;  i += blockDim.x) {
        float s = 0.f;
        #pragma unroll
        for (int p = 0; p < 9; p++) s += Wm[i * 9 + p];
        gPrep[OFF_BM + i] = dupf(0.5f * bm[i] + 0.25f * s);
    }
    for (int i = t; i < 16;  i += blockDim.x) gPrep[OFF_WO + i] = dupf(0.5f * Wo[i]);
    for (int i = t; i < 4;   i += blockDim.x) {
        float s = 0.f;
        #pragma unroll
        for (int p = 0; p < 4; p++) s += Wo[i * 4 + p];
        gPrep[OFF_BO + i] = dupf(bo[i] + 0.5f * s);
    }
}

__device__ __forceinline__ ull ffma2(ull a, ull b, ull c) {
    ull d;
    asm("fma.rn.f32x2 %0, %1, %2, %3;" : "=l"(d) : "l"(a), "l"(b), "l"(c));
    return d;
}
__device__ __forceinline__ ull pack2(float lo, float hi) {
    ull r;
    asm("mov.b64 %0, {%1, %2};" : "=l"(r) : "f"(lo), "f"(hi));
    return r;
}
__device__ __forceinline__ void unpack2(ull v, float& lo, float& hi) {
    asm("mov.b64 {%0, %1}, %2;" : "=f"(lo), "=f"(hi) : "l"(v));
}
__device__ __forceinline__ ull tanh2(ull v) {
    float lo, hi;
    unpack2(v, lo, hi);
    asm("tanh.approx.f32 %0, %0;" : "+f"(lo));
    asm("tanh.approx.f32 %0, %0;" : "+f"(hi));
    return pack2(lo, hi);
}

__global__ __launch_bounds__(NTHREADS, 5)
void olcnn_kernel(const float* __restrict__ x, float* __restrict__ out) {
    extern __shared__ __half s_h[];   // ELEMS*KDIM halfs = 41472 B, element-major

    const int tid = threadIdx.x;
    const long long blk = blockIdx.x;

    // ---- Stage: coalesced float4 read, fp16 convert, element-major store ----
    {
        const float4* __restrict__ src =
            reinterpret_cast<const float4*>(x + blk * (long long)(ELEMS * KDIM));
        for (int i = tid; i < (ELEMS * KDIM) / 4; i += NTHREADS) {
            float4 v = src[i];
            int f = i * 4;
            s_h[f + 0] = __float2half_rn(v.x);
            s_h[f + 1] = __float2half_rn(v.y);
            s_h[f + 2] = __float2half_rn(v.z);
            s_h[f + 3] = __float2half_rn(v.w);
        }
    }
    __syncthreads();

    // thread handles elements e0=tid, e1=tid+128
    const __half* __restrict__ xa = s_h + tid * KDIM;
    const __half* __restrict__ xb = s_h + (tid + NTHREADS) * KDIM;

    ull lg[4];
    #pragma unroll
    for (int c = 0; c < 4; c++) lg[c] = cPrep[OFF_BO + c];

    #pragma unroll
    for (int G = 0; G < 3; G++) {
        ull h[9];

        #pragma unroll
        for (int s = 0; s < 3; s++) {
            const int g  = 3 * G + s;
            const int gr = g / 3, gc = g % 3;

            ull px[9];
            #pragma unroll
            for (int p = 0; p < 9; p++) {
                const int k = (3 * gr + p / 3) * 9 + (3 * gc + p % 3);
                px[p] = pack2(__half2float(xa[k]), __half2float(xb[k]));
            }

            // conv: 9 kernels -> tanh
            ull f[9];
            #pragma unroll
            for (int k = 0; k < 9; k++) {
                ull acc = cPrep[OFF_BC + g * 9 + k];
                #pragma unroll
                for (int p = 0; p < 9; p++)
                    acc = ffma2(px[p], cPrep[OFF_WC + (g * 9 + k) * 9 + p], acc);
                f[k] = tanh2(acc);
            }

            // hidden: 3 neurons -> tanh
            #pragma unroll
            for (int n = 0; n < 3; n++) {
                ull acc = cPrep[OFF_BH + g * 3 + n];
                #pragma unroll
                for (int k = 0; k < 9; k++)
                    acc = ffma2(f[k], cPrep[OFF_WH + (g * 3 + n) * 9 + k], acc);
                h[s * 3 + n] = tanh2(acc);
            }
        }

        // middle group G: 4 neurons -> tanh -> fold into logits
        #pragma unroll
        for (int n = 0; n < 4; n++) {
            ull acc = cPrep[OFF_BM + G * 4 + n];
            #pragma unroll
            for (int p = 0; p < 9; p++)
                acc = ffma2(h[p], cPrep[OFF_WM + (G * 4 + n) * 9 + p], acc);
            ull mv = tanh2(acc);

            lg[G] = ffma2(mv, cPrep[OFF_WO + G * 4 + n], lg[G]);
            if (G == 0)
                lg[3] = ffma2(mv, cPrep[OFF_WO + 3 * 4 + n], lg[3]);
        }
    }

    float lo[4], hi[4];
    #pragma unroll
    for (int c = 0; c < 4; c++) unpack2(lg[c], lo[c], hi[c]);

    float4* __restrict__ o4 = reinterpret_cast<float4*>(out) + blk * ELEMS;
    o4[tid]            = make_float4(lo[0], lo[1], lo[2], lo[3]);
    o4[tid + NTHREADS] = make_float4(hi[0], hi[1], hi[2], hi[3]);
}

extern "C" void kernel_launch(void* const* d_in, const int* in_sizes, int n_in,
                              void* d_out, int out_size) {
    const float* x = (const float*)d_in[0];

    prep_kernel<<<1, 256>>>((const float*)d_in[1], (const float*)d_in[2],
                            (const float*)d_in[3], (const float*)d_in[4],
                            (const float*)d_in[5], (const float*)d_in[6],
                            (const float*)d_in[7], (const float*)d_in[8]);
    void* gptr = nullptr;
    cudaGetSymbolAddress(&gptr, gPrep);
    cudaMemcpyToSymbolAsync(cPrep, gptr, NPREP * sizeof(ull), 0,
                            cudaMemcpyDeviceToDevice, 0);

    const int B = in_sizes[0] / KDIM;        // 524288
    const int nblocks = B / ELEMS;           // 2048

    const int smem = ELEMS * KDIM * (int)sizeof(__half);   // 41472 B
    // THE fix: allow 5 resident blocks (207KB) — default carveout capped R3 at 2.
    cudaFuncSetAttribute(olcnn_kernel, cudaFuncAttributeMaxDynamicSharedMemorySize, smem);
    cudaFuncSetAttribute(olcnn_kernel, cudaFuncAttributePreferredSharedMemoryCarveout, 100);

    olcnn_kernel<<<nblocks, NTHREADS, smem>>>(x, (float*)d_out);
}